// round 15
// baseline (speedup 1.0000x reference)
#include <cuda_runtime.h>
#include <cuda_fp16.h>
#include <math.h>
#include <stdint.h>

#define BB 4
#define SS 2048
#define HH 2048
#define NHH 8
#define DD 256
#define QKVW 2560            // (8 + 2*1) * 256
#define MROWS (BB * SS)      // 8192

// ---------------------------------------------------------------------------
// Scratch (allocation-free rule: device globals)
// ---------------------------------------------------------------------------
__device__ __align__(16) __half g_hid[MROWS * HH];            // hidden fp16
__device__ __align__(16) __half g_wqkv[QKVW * HH];            // transposed+permuted [N][K]
__device__ __align__(16) __half g_wo[HH * HH];                // transposed [N][K]
__device__ __align__(16) __half g_atn[MROWS * HH];            // attention out fp16
__device__ __align__(16) __half g_q[(size_t)BB * NHH * SS * DD];
__device__ __align__(16) __half g_k[(size_t)BB * SS * DD];
__device__ __align__(16) __half g_v[(size_t)BB * SS * DD];

// ---------------------------------------------------------------------------
// helpers
// ---------------------------------------------------------------------------
__device__ __forceinline__ uint32_t smem_u32(const void* p) {
    uint32_t a;
    asm("{ .reg .u64 t; cvta.to.shared.u64 t, %1; cvt.u32.u64 %0, t; }"
        : "=r"(a) : "l"(p));
    return a;
}

__device__ __forceinline__ void ldsm_x4(uint32_t (&r)[4], uint32_t addr) {
    asm volatile("ldmatrix.sync.aligned.m8n8.x4.shared.b16 {%0,%1,%2,%3}, [%4];"
                 : "=r"(r[0]), "=r"(r[1]), "=r"(r[2]), "=r"(r[3]) : "r"(addr));
}

__device__ __forceinline__ void ldsm_x4_t(uint32_t (&r)[4], uint32_t addr) {
    asm volatile("ldmatrix.sync.aligned.m8n8.x4.trans.shared.b16 {%0,%1,%2,%3}, [%4];"
                 : "=r"(r[0]), "=r"(r[1]), "=r"(r[2]), "=r"(r[3]) : "r"(addr));
}

__device__ __forceinline__ void mma_f16(float (&d)[4], const uint32_t (&a)[4],
                                        const uint32_t* b) {
    asm volatile(
        "mma.sync.aligned.m16n8k16.row.col.f32.f16.f16.f32 "
        "{%0,%1,%2,%3}, {%4,%5,%6,%7}, {%8,%9}, {%0,%1,%2,%3};"
        : "+f"(d[0]), "+f"(d[1]), "+f"(d[2]), "+f"(d[3])
        : "r"(a[0]), "r"(a[1]), "r"(a[2]), "r"(a[3]), "r"(b[0]), "r"(b[1]));
}

__device__ __forceinline__ void cp16(uint32_t dst, const void* src) {
    asm volatile("cp.async.cg.shared.global [%0], [%1], 16;"
                 :: "r"(dst), "l"(src) : "memory");
}

__device__ __forceinline__ uint32_t pk_h2(float a, float b) {
    __half2 t = __floats2half2_rn(a, b);
    return *reinterpret_cast<uint32_t*>(&t);
}

// ---------------------------------------------------------------------------
// GEMM config: block 64x256x32, 256 threads (2Mx4N), warp 32x64, 3-stage.
// ---------------------------------------------------------------------------
#define ROWB 80
#define GA_T (64 * ROWB)
#define GB_T (256 * ROWB)
#define G1STAGE (GA_T + GB_T)
#define GEMM1_SMEM (3 * G1STAGE)

// ---------------------------------------------------------------------------
// QKV GEMM with fused RoPE epilogue (verified R13/R14).
// ---------------------------------------------------------------------------
__global__ __launch_bounds__(256, 2) void hmma_gemmqkv_kernel(
    const __half* __restrict__ A, const __half* __restrict__ Bw,
    const int* __restrict__ positions,
    __half* __restrict__ qq, __half* __restrict__ kk, __half* __restrict__ vv)
{
    extern __shared__ char gsm[];
    const uint32_t base = smem_u32(gsm);
    const int K = HH;

    const int tid = threadIdx.x;
    const int lane = tid & 31;
    const int wid = tid >> 5;
    const int warp_m = wid & 1;
    const int warp_n = wid >> 1;
    const int row0 = blockIdx.y * 64, col0 = blockIdx.x * 256;

    float acc[2][8][4];
#pragma unroll
    for (int i = 0; i < 2; i++)
#pragma unroll
        for (int j = 0; j < 8; j++)
#pragma unroll
            for (int e = 0; e < 4; e++) acc[i][j][e] = 0.f;

    const int nch = K >> 5;

    auto load_stage = [&](int st, int k0) {
        const uint32_t sb = base + st * G1STAGE;
#pragma unroll
        for (int i2 = 0; i2 < 5; i2++) {
            int g = tid + (i2 << 8);
            const __half* src;
            uint32_t dst;
            if (g < 256) {
                int r = g >> 2;
                int kq = g & 3;
                src = A + (size_t)(row0 + r) * K + k0 + (kq << 3);
                dst = sb + r * ROWB + (kq << 4);
            } else {
                int g2 = g - 256;
                int r = g2 >> 2;
                int kq = g2 & 3;
                src = Bw + (size_t)(col0 + r) * K + k0 + (kq << 3);
                dst = sb + GA_T + r * ROWB + (kq << 4);
            }
            cp16(dst, src);
        }
        asm volatile("cp.async.commit_group;" ::: "memory");
    };

    load_stage(0, 0);
    load_stage(1, 32);

    int st = 0;
    for (int c = 0; c < nch; c++) {
        if (c == nch - 1) { asm volatile("cp.async.wait_group 0;" ::: "memory"); }
        else              { asm volatile("cp.async.wait_group 1;" ::: "memory"); }
        __syncthreads();

        if (c + 2 < nch) {
            int pst = st + 2; if (pst >= 3) pst -= 3;
            load_stage(pst, (c + 2) << 5);
        }

        const uint32_t sb = base + st * G1STAGE;
        const uint32_t aH = sb, bT = sb + GA_T;

#pragma unroll
        for (int ks = 0; ks < 2; ks++) {
            uint32_t ah[2][4], bw[8][2];
            const int arow = warp_m * 32 + (lane & 15);
            const uint32_t akoff = (ks << 5) + ((lane >> 4) << 4);
#pragma unroll
            for (int i = 0; i < 2; i++)
                ldsm_x4(ah[i], aH + (uint32_t)(arow + i * 16) * ROWB + akoff);
            const int quad = lane >> 3, wi = lane & 7;
#pragma unroll
            for (int t = 0; t < 4; t++) {
                int ntile = 2 * t + (quad >> 1);
                int brow = warp_n * 64 + ntile * 8 + wi;
                uint32_t bd = bT + (uint32_t)brow * ROWB + (ks << 5) + ((quad & 1) << 4);
                uint32_t r4[4];
                ldsm_x4(r4, bd);
                bw[2 * t][0] = r4[0]; bw[2 * t][1] = r4[1];
                bw[2 * t + 1][0] = r4[2]; bw[2 * t + 1][1] = r4[3];
            }
#pragma unroll
            for (int i = 0; i < 2; i++)
#pragma unroll
                for (int j = 0; j < 8; j++)
                    mma_f16(acc[i][j], ah[i], bw[j]);
        }
        if (++st >= 3) st -= 3;
    }

    // fused RoPE epilogue
    const int rb = row0 + warp_m * 32 + (lane >> 2);
    const int head = blockIdx.x;
    const int pb = warp_n * 64 + (lane & 3) * 2;

    if (head == 9) {
#pragma unroll
        for (int i = 0; i < 2; i++)
#pragma unroll
            for (int j = 0; j < 8; j++) {
                int colp = pb + j * 8;
                uint32_t h01 = pk_h2(acc[i][j][0], acc[i][j][1]);
                uint32_t h23 = pk_h2(acc[i][j][2], acc[i][j][3]);
                *(uint32_t*)&vv[(size_t)(rb + i * 16) * DD + colp] = h01;
                *(uint32_t*)&vv[(size_t)(rb + i * 16 + 8) * DD + colp] = h23;
            }
    } else {
        float inv[8];
        const float LOG_THETA = 9.210340371976184f;
#pragma unroll
        for (int j = 0; j < 8; j++) {
            int m = (pb + j * 8) >> 1;
            inv[j] = expf(-LOG_THETA * ((float)m * (1.0f / 128.0f)));
        }
        const float qscale = (head < 8) ? 0.0625f : 1.0f;
#pragma unroll
        for (int i = 0; i < 2; i++) {
#pragma unroll
            for (int half = 0; half < 2; half++) {
                int r = rb + i * 16 + half * 8;
                int s = r & (SS - 1);
                int bidx = r >> 11;
                float pos = (float)positions[s];
                size_t ooff;
                __half* outp;
                if (head < 8) {
                    ooff = ((size_t)(bidx * NHH + head) * SS + s) * DD;
                    outp = qq;
                } else {
                    ooff = (size_t)r * DD;
                    outp = kk;
                }
#pragma unroll
                for (int j = 0; j < 8; j++) {
                    float a = acc[i][j][half * 2 + 0];
                    float b = acc[i][j][half * 2 + 1];
                    float ang = pos * inv[j];
                    float sn, cs;
                    sincosf(ang, &sn, &cs);
                    float y1 = (a * cs - b * sn) * qscale;
                    float y2 = (b * cs + a * sn) * qscale;
                    int m = (pb + j * 8) >> 1;
                    outp[ooff + m]       = __float2half_rn(y1);
                    outp[ooff + m + 128] = __float2half_rn(y2);
                }
            }
        }
    }
}

// ---------------------------------------------------------------------------
// Plain single-pass GEMM (O-projection), fp32 out (verified).
// ---------------------------------------------------------------------------
__global__ __launch_bounds__(256, 2) void hmma_gemm1_kernel(
    const __half* __restrict__ A, const __half* __restrict__ Bw,
    float* __restrict__ C, int M, int N, int K)
{
    extern __shared__ char gsm[];
    const uint32_t base = smem_u32(gsm);

    const int tid = threadIdx.x;
    const int lane = tid & 31;
    const int wid = tid >> 5;
    const int warp_m = wid & 1;
    const int warp_n = wid >> 1;
    const int row0 = blockIdx.y * 64, col0 = blockIdx.x * 256;

    float acc[2][8][4];
#pragma unroll
    for (int i = 0; i < 2; i++)
#pragma unroll
        for (int j = 0; j < 8; j++)
#pragma unroll
            for (int e = 0; e < 4; e++) acc[i][j][e] = 0.f;

    const int nch = K >> 5;

    auto load_stage = [&](int st, int k0) {
        const uint32_t sb = base + st * G1STAGE;
#pragma unroll
        for (int i2 = 0; i2 < 5; i2++) {
            int g = tid + (i2 << 8);
            const __half* src;
            uint32_t dst;
            if (g < 256) {
                int r = g >> 2;
                int kq = g & 3;
                src = A + (size_t)(row0 + r) * K + k0 + (kq << 3);
                dst = sb + r * ROWB + (kq << 4);
            } else {
                int g2 = g - 256;
                int r = g2 >> 2;
                int kq = g2 & 3;
                src = Bw + (size_t)(col0 + r) * K + k0 + (kq << 3);
                dst = sb + GA_T + r * ROWB + (kq << 4);
            }
            cp16(dst, src);
        }
        asm volatile("cp.async.commit_group;" ::: "memory");
    };

    load_stage(0, 0);
    load_stage(1, 32);

    int st = 0;
    for (int c = 0; c < nch; c++) {
        if (c == nch - 1) { asm volatile("cp.async.wait_group 0;" ::: "memory"); }
        else              { asm volatile("cp.async.wait_group 1;" ::: "memory"); }
        __syncthreads();

        if (c + 2 < nch) {
            int pst = st + 2; if (pst >= 3) pst -= 3;
            load_stage(pst, (c + 2) << 5);
        }

        const uint32_t sb = base + st * G1STAGE;
        const uint32_t aH = sb, bT = sb + GA_T;

#pragma unroll
        for (int ks = 0; ks < 2; ks++) {
            uint32_t ah[2][4], bw[8][2];
            const int arow = warp_m * 32 + (lane & 15);
            const uint32_t akoff = (ks << 5) + ((lane >> 4) << 4);
#pragma unroll
            for (int i = 0; i < 2; i++)
                ldsm_x4(ah[i], aH + (uint32_t)(arow + i * 16) * ROWB + akoff);
            const int quad = lane >> 3, wi = lane & 7;
#pragma unroll
            for (int t = 0; t < 4; t++) {
                int ntile = 2 * t + (quad >> 1);
                int brow = warp_n * 64 + ntile * 8 + wi;
                uint32_t bd = bT + (uint32_t)brow * ROWB + (ks << 5) + ((quad & 1) << 4);
                uint32_t r4[4];
                ldsm_x4(r4, bd);
                bw[2 * t][0] = r4[0]; bw[2 * t][1] = r4[1];
                bw[2 * t + 1][0] = r4[2]; bw[2 * t + 1][1] = r4[3];
            }
#pragma unroll
            for (int i = 0; i < 2; i++)
#pragma unroll
                for (int j = 0; j < 8; j++)
                    mma_f16(acc[i][j], ah[i], bw[j]);
        }
        if (++st >= 3) st -= 3;
    }

    const int rb = row0 + warp_m * 32 + (lane >> 2);
    const int cb = col0 + warp_n * 64 + (lane & 3) * 2;
#pragma unroll
    for (int i = 0; i < 2; i++)
#pragma unroll
        for (int j = 0; j < 8; j++) {
            float* p0 = C + (size_t)(rb + i * 16) * N + cb + j * 8;
            float* p1 = C + (size_t)(rb + i * 16 + 8) * N + cb + j * 8;
            *(float2*)p0 = make_float2(acc[i][j][0], acc[i][j][1]);
            *(float2*)p1 = make_float2(acc[i][j][2], acc[i][j][3]);
        }
}

// ---------------------------------------------------------------------------
// fp32 -> fp16 convert
// ---------------------------------------------------------------------------
__global__ void convh_kernel(const float* __restrict__ x,
                             __half* __restrict__ y, int n4)
{
    int i = blockIdx.x * blockDim.x + threadIdx.x;
    if (i >= n4) return;
    float4 v = ((const float4*)x)[i];
    __half hv[4];
    hv[0] = __float2half_rn(v.x);
    hv[1] = __float2half_rn(v.y);
    hv[2] = __float2half_rn(v.z);
    hv[3] = __float2half_rn(v.w);
    *(uint2*)&y[(size_t)i * 4] = *(uint2*)hv;
}

// ---------------------------------------------------------------------------
// w_o transpose + convert
// ---------------------------------------------------------------------------
__global__ void tconvh_kernel(const float* __restrict__ x,
                              __half* __restrict__ w, int R, int Cn)
{
    __shared__ float t[32][33];
    int bc = blockIdx.x * 32, br = blockIdx.y * 32;
    int tx = threadIdx.x, ty = threadIdx.y;
#pragma unroll
    for (int j = 0; j < 32; j += 8)
        t[ty + j][tx] = x[(size_t)(br + ty + j) * Cn + bc + tx];
    __syncthreads();
#pragma unroll
    for (int j = 0; j < 32; j += 8) {
        int orow = bc + ty + j;
        int ocol = br + tx;
        w[(size_t)orow * R + ocol] = __float2half_rn(t[tx][ty + j]);
    }
}

// ---------------------------------------------------------------------------
// w_qkv transpose + convert + RoPE column permutation (verified R13)
// ---------------------------------------------------------------------------
__global__ void tconvh_perm_kernel(const float* __restrict__ x,
                                   __half* __restrict__ w, int R, int Cn)
{
    __shared__ float t[32][33];
    int bc = blockIdx.x * 32, br = blockIdx.y * 32;
    int tx = threadIdx.x, ty = threadIdx.y;
#pragma unroll
    for (int j = 0; j < 32; j += 8)
        t[ty + j][tx] = x[(size_t)(br + ty + j) * Cn + bc + tx];
    __syncthreads();
#pragma unroll
    for (int j = 0; j < 32; j += 8) {
        int c = bc + ty + j;
        int ocol = br + tx;
        int p;
        if (c < 2304) {
            int hb = c & ~255;
            int cp = c - hb;
            p = hb + ((cp < 128) ? (2 * cp) : (2 * (cp - 128) + 1));
        } else {
            p = c;
        }
        w[(size_t)p * R + ocol] = __float2half_rn(t[tx][ty + j]);
    }
}

// ---------------------------------------------------------------------------
// HMMA flash attention v4: Br=128, Bc=32, 256 threads (8 warps).
// Double-buffered K+V; barrier-light mainloop; S-phase accumulators SPLIT
// into even/odd-ks banks (8 chains/warp instead of 4) to halve the
// dependent-MMA latency exposure.
// ---------------------------------------------------------------------------
#define KSTR 528
#define PSTR 80
#define FQ 0
#define FKV0 (FQ + 128 * KSTR)
#define FKV1 (FKV0 + 64 * KSTR)
#define FP (FKV1 + 64 * KSTR)
#define FLASH_SMEM (FP + 128 * PSTR)

__global__ __launch_bounds__(256) void flash_hmma_kernel(
    const __half* __restrict__ Qp, const __half* __restrict__ Kp,
    const __half* __restrict__ Vp, __half* __restrict__ Op)
{
    extern __shared__ char fsm[];
    const uint32_t base = smem_u32(fsm);
    const int qt = (gridDim.x - 1) - blockIdx.x;
    const int h = blockIdx.y, b = blockIdx.z;
    const int tid = threadIdx.x, lane = tid & 31, w = tid >> 5;
    const int q0 = qt * 128;
    const int nj = (q0 + 128) >> 5;

    const __half* qp = Qp + ((size_t)(b * NHH + h) * SS + q0) * DD;
    const __half* kp = Kp + (size_t)b * SS * DD;
    const __half* vp = Vp + (size_t)b * SS * DD;

    {
#pragma unroll
        for (int i = 0; i < 16; i++) {
            int g = tid + (i << 8);
            int r = g >> 5, cq = g & 31;
            cp16(base + FQ + r * KSTR + (cq << 4),
                 qp + (size_t)r * DD + (cq << 3));
        }
        asm volatile("cp.async.commit_group;" ::: "memory");
    }

    auto ldkv = [&](int buf, int c0) {
        uint32_t bb = base + (buf ? FKV1 : FKV0);
#pragma unroll
        for (int i = 0; i < 8; i++) {
            int g = tid + (i << 8);
            int r = g >> 5, cq = g & 31;
            const __half* p = (r < 32) ? (kp + (size_t)(c0 + r) * DD)
                                       : (vp + (size_t)(c0 + r - 32) * DD);
            cp16(bb + r * KSTR + (cq << 4), p + (cq << 3));
        }
        asm volatile("cp.async.commit_group;" ::: "memory");
    };

    ldkv(0, 0);
    if (nj > 1) ldkv(1, 32);

    float acc[32][4];
#pragma unroll
    for (int t = 0; t < 32; t++)
#pragma unroll
        for (int e = 0; e < 4; e++) acc[t][e] = 0.f;
    float m0 = -1e30f, m1 = -1e30f, l0 = 0.f, l1 = 0.f;

    const uint32_t aQbase = base + FQ + (w * 16 + (lane & 15)) * KSTR + ((lane >> 4) << 4);
    const int quad = lane >> 3, wi = lane & 7;
    const uint32_t kOff = ((quad >> 1) * 8 + wi) * KSTR + ((quad & 1) << 4);
    const uint32_t vOff = 32 * KSTR + ((lane & 7) + ((lane >> 3) & 1) * 8) * KSTR
                        + (lane >> 4) * 16;
    const uint32_t aPbase = base + FP + (w * 16 + (lane & 15)) * PSTR + ((lane >> 4) << 4);
    const uint32_t pstore = base + FP + (w * 16 + (lane >> 2)) * PSTR + (lane & 3) * 4;

    for (int jt = 0; jt < nj; jt++) {
        const int c0 = jt * 32;
        const uint32_t bb = base + ((jt & 1) ? FKV1 : FKV0);
        if (jt + 1 < nj) { asm volatile("cp.async.wait_group 1;" ::: "memory"); }
        else             { asm volatile("cp.async.wait_group 0;" ::: "memory"); }
        __syncthreads();

        // ---------------- S = Q K^T, split accumulator banks ----------------
        float sa[4][4], sb2[4][4];
#pragma unroll
        for (int t = 0; t < 4; t++)
#pragma unroll
            for (int e = 0; e < 4; e++) { sa[t][e] = 0.f; sb2[t][e] = 0.f; }

#pragma unroll
        for (int ks2 = 0; ks2 < 8; ks2++) {
            // even ks -> sa, odd ks -> sb2 : 8 independent chains
            uint32_t ah0[4], ah1[4];
            ldsm_x4(ah0, aQbase + (2 * ks2) * 32);
            ldsm_x4(ah1, aQbase + (2 * ks2 + 1) * 32);
#pragma unroll
            for (int np = 0; np < 2; np++) {
                uint32_t b0[4], b1[4];
                ldsm_x4(b0, bb + kOff + np * 16 * KSTR + (2 * ks2) * 32);
                ldsm_x4(b1, bb + kOff + np * 16 * KSTR + (2 * ks2 + 1) * 32);
                mma_f16(sa[2 * np],      ah0, b0);
                mma_f16(sb2[2 * np],     ah1, b1);
                mma_f16(sa[2 * np + 1],  ah0, b0 + 2);
                mma_f16(sb2[2 * np + 1], ah1, b1 + 2);
            }
        }
        float sacc[4][4];
#pragma unroll
        for (int t = 0; t < 4; t++)
#pragma unroll
            for (int e = 0; e < 4; e++) sacc[t][e] = sa[t][e] + sb2[t][e];

        // ---------------- softmax (warp-local) ----------------
        const int colb = c0 + (lane & 3) * 2;
        const int row0g = q0 + w * 16 + (lane >> 2);
        const int row1g = row0g + 8;
        if (c0 + 31 > q0) {
#pragma unroll
            for (int t = 0; t < 4; t++) {
                int cg = colb + t * 8;
#pragma unroll
                for (int e = 0; e < 4; e++) {
                    int c = cg + (e & 1);
                    int rg = (e < 2) ? row0g : row1g;
                    if (c > rg) sacc[t][e] = -1e30f;
                }
            }
        }
        float mx0 = -1e30f, mx1 = -1e30f;
#pragma unroll
        for (int t = 0; t < 4; t++) {
            mx0 = fmaxf(mx0, fmaxf(sacc[t][0], sacc[t][1]));
            mx1 = fmaxf(mx1, fmaxf(sacc[t][2], sacc[t][3]));
        }
        mx0 = fmaxf(mx0, __shfl_xor_sync(0xffffffffu, mx0, 1));
        mx0 = fmaxf(mx0, __shfl_xor_sync(0xffffffffu, mx0, 2));
        mx1 = fmaxf(mx1, __shfl_xor_sync(0xffffffffu, mx1, 1));
        mx1 = fmaxf(mx1, __shfl_xor_sync(0xffffffffu, mx1, 2));

        float mn0 = fmaxf(m0, mx0), mn1 = fmaxf(m1, mx1);
        float a0 = __expf(m0 - mn0), a1 = __expf(m1 - mn1);
        m0 = mn0; m1 = mn1;
        float s0 = 0.f, s1 = 0.f;
#pragma unroll
        for (int t = 0; t < 4; t++) {
            float p0 = __expf(sacc[t][0] - mn0);
            float p1 = __expf(sacc[t][1] - mn0);
            float p2 = __expf(sacc[t][2] - mn1);
            float p3 = __expf(sacc[t][3] - mn1);
            s0 += p0 + p1; s1 += p2 + p3;
            uint32_t h01 = pk_h2(p0, p1);
            uint32_t h23 = pk_h2(p2, p3);
            asm volatile("st.shared.b32 [%0], %1;" :: "r"(pstore + t * 16), "r"(h01) : "memory");
            asm volatile("st.shared.b32 [%0], %1;" :: "r"(pstore + 8 * PSTR + t * 16), "r"(h23) : "memory");
        }
        s0 += __shfl_xor_sync(0xffffffffu, s0, 1);
        s0 += __shfl_xor_sync(0xffffffffu, s0, 2);
        s1 += __shfl_xor_sync(0xffffffffu, s1, 1);
        s1 += __shfl_xor_sync(0xffffffffu, s1, 2);
        l0 = l0 * a0 + s0;
        l1 = l1 * a1 + s1;
        bool noresc = __all_sync(0xffffffffu, (a0 == 1.0f) && (a1 == 1.0f));
        if (!noresc) {
#pragma unroll
            for (int t = 0; t < 32; t++) {
                acc[t][0] *= a0; acc[t][1] *= a0;
                acc[t][2] *= a1; acc[t][3] *= a1;
            }
        }
        __syncwarp();

        // ---------------- O += P V ----------------
#pragma unroll
        for (int ks = 0; ks < 2; ks++) {
            uint32_t ph4[4];
            ldsm_x4(ph4, aPbase + ks * 32);
#pragma unroll
            for (int np = 0; np < 16; np++) {
                uint32_t vh4[4];
                ldsm_x4_t(vh4, bb + vOff + ks * 16 * KSTR + np * 32);
                mma_f16(acc[2 * np],     ph4, vh4);
                mma_f16(acc[2 * np + 1], ph4, vh4 + 2);
            }
        }

        __syncthreads();
        if (jt + 2 < nj) ldkv(jt & 1, c0 + 64);
    }

    float inv0 = 1.0f / l0, inv1 = 1.0f / l1;
    size_t ob0 = ((size_t)(b * SS) + q0 + w * 16 + (lane >> 2)) * HH + h * DD + (lane & 3) * 2;
    size_t ob1 = ob0 + 8 * (size_t)HH;
#pragma unroll
    for (int t = 0; t < 32; t++) {
        uint32_t h01 = pk_h2(acc[t][0] * inv0, acc[t][1] * inv0);
        uint32_t h23 = pk_h2(acc[t][2] * inv1, acc[t][3] * inv1);
        *(uint32_t*)&Op[ob0 + t * 8] = h01;
        *(uint32_t*)&Op[ob1 + t * 8] = h23;
    }
}

// ---------------------------------------------------------------------------
extern "C" void kernel_launch(void* const* d_in, const int* in_sizes, int n_in,
                              void* d_out, int out_size)
{
    const float* hidden    = (const float*)d_in[0];
    const int*   positions = (const int*)d_in[1];
    const float* w_qkv     = (const float*)d_in[2];
    const float* w_o       = (const float*)d_in[3];
    float* out = (float*)d_out;

    __half *hid_p, *wqkv_p, *wo_p, *atn_p;
    __half *q_p, *k_p, *v_p;
    cudaGetSymbolAddress((void**)&hid_p, g_hid);
    cudaGetSymbolAddress((void**)&wqkv_p, g_wqkv);
    cudaGetSymbolAddress((void**)&wo_p, g_wo);
    cudaGetSymbolAddress((void**)&atn_p, g_atn);
    cudaGetSymbolAddress((void**)&q_p, g_q);
    cudaGetSymbolAddress((void**)&k_p, g_k);
    cudaGetSymbolAddress((void**)&v_p, g_v);

    cudaFuncSetAttribute(hmma_gemmqkv_kernel,
                         cudaFuncAttributeMaxDynamicSharedMemorySize, GEMM1_SMEM);
    cudaFuncSetAttribute(hmma_gemm1_kernel,
                         cudaFuncAttributeMaxDynamicSharedMemorySize, GEMM1_SMEM);
    cudaFuncSetAttribute(flash_hmma_kernel,
                         cudaFuncAttributeMaxDynamicSharedMemorySize, FLASH_SMEM);

    // 1) convert hidden -> fp16
    {
        int n4 = MROWS * HH / 4;
        convh_kernel<<<(n4 + 255) / 256, 256>>>(hidden, hid_p, n4);
    }
    // 2) transpose+convert+permute w_qkv
    tconvh_perm_kernel<<<dim3(QKVW / 32, HH / 32), dim3(32, 8)>>>(w_qkv, wqkv_p, HH, QKVW);

    // 3) QKV projection with fused RoPE epilogue
    hmma_gemmqkv_kernel<<<dim3(QKVW / 256, MROWS / 64), 256, GEMM1_SMEM>>>(
        hid_p, wqkv_p, positions, q_p, k_p, v_p);

    // 4) HMMA flash attention v4 (split S-chains)
    {
        dim3 grid2(SS / 128, NHH, BB);
        flash_hmma_kernel<<<grid2, 256, FLASH_SMEM>>>(q_p, k_p, v_p, atn_p);
    }

    // 5) transpose+convert w_o
    tconvh_kernel<<<dim3(HH / 32, HH / 32), dim3(32, 8)>>>(w_o, wo_p, HH, HH);

    // 6) Output projection
    hmma_gemm1_kernel<<<dim3(HH / 256, MROWS / 64), 256, GEMM1_SMEM>>>(
        atn_p, wo_p, out, MROWS, HH, HH);
}